// round 1
// baseline (speedup 1.0000x reference)
#include <cuda_runtime.h>
#include <cstdint>
#include <cstddef>

#define NB   4096
#define HH   512
#define G4   2048
#define NSEQ 100
#define NJ   63
#define IN0  254
#define IN0P 256

// ---------------- device scratch (no allocations allowed) ----------------
__device__ float g_x   [NB * IN0P];            // padded combined input (tf32-rounded)
__device__ float g_x0  [NB * G4];              // x @ W_ih0^T + b_ih0 + b_hh0
__device__ float g_h0  [2][NB * HH];           // ping-pong h0 (tf32-rounded)
__device__ float g_h1  [2][NB * HH];           // ping-pong h1 (tf32-rounded)
__device__ float g_c0  [NB * HH];
__device__ float g_c1  [NB * HH];
__device__ float g_Wih0[G4 * IN0P];            // tf32-rounded, K padded to 256
__device__ float g_Whh0[G4 * HH];              // tf32-rounded
__device__ float g_W1  [G4 * 2 * HH];          // [W_ih1 | W_hh1], tf32-rounded
__device__ float g_bias0[G4];                  // b_ih0 + b_hh0
__device__ float g_bias1[G4];                  // b_ih1 + b_hh1
__device__ float g_y   [(size_t)NSEQ * NB * NJ]; // staging [t][b][j]

// ---------------- helpers ----------------
__device__ __forceinline__ float to_tf32(float x) {
    uint32_t u;
    asm("cvt.rna.tf32.f32 %0, %1;" : "=r"(u) : "f"(x));
    return __uint_as_float(u);
}
__device__ __forceinline__ float sigm(float x) { return 1.f / (1.f + expf(-x)); }

__device__ __forceinline__ void mma_tf32(float (&c)[4],
    uint32_t a0, uint32_t a1, uint32_t a2, uint32_t a3, uint32_t b0, uint32_t b1)
{
    asm volatile(
        "mma.sync.aligned.m16n8k8.row.col.f32.tf32.tf32.f32 "
        "{%0,%1,%2,%3}, {%4,%5,%6,%7}, {%8,%9}, {%0,%1,%2,%3};\n"
        : "+f"(c[0]), "+f"(c[1]), "+f"(c[2]), "+f"(c[3])
        : "r"(a0), "r"(a1), "r"(a2), "r"(a3), "r"(b0), "r"(b1));
}

// ---------------- prologue kernels ----------------
__global__ void prep_weights_kernel(
    const float* __restrict__ Wih0, const float* __restrict__ Whh0,
    const float* __restrict__ bih0, const float* __restrict__ bhh0,
    const float* __restrict__ Wih1, const float* __restrict__ Whh1,
    const float* __restrict__ bih1, const float* __restrict__ bhh1)
{
    int i0 = blockIdx.x * blockDim.x + threadIdx.x;
    int st = gridDim.x * blockDim.x;
    for (int i = i0; i < G4 * IN0P; i += st) {
        int n = i >> 8, k = i & 255;
        g_Wih0[i] = (k < IN0) ? to_tf32(Wih0[n * IN0 + k]) : 0.f;
    }
    for (int i = i0; i < G4 * HH; i += st) g_Whh0[i] = to_tf32(Whh0[i]);
    for (int i = i0; i < G4 * 2 * HH; i += st) {
        int n = i >> 10, k = i & 1023;
        g_W1[i] = to_tf32(k < HH ? Wih1[n * HH + k] : Whh1[n * HH + k - HH]);
    }
    for (int i = i0; i < G4; i += st) {
        g_bias0[i] = bih0[i] + bhh0[i];
        g_bias1[i] = bih1[i] + bhh1[i];
    }
}

__global__ void build_x_init_kernel(
    const int* __restrict__ sl, const int* __restrict__ el,
    const float* __restrict__ sc, const float* __restrict__ ec,
    const float* __restrict__ emb)
{
    int i0 = blockIdx.x * blockDim.x + threadIdx.x;
    int st = gridDim.x * blockDim.x;
    for (int i = i0; i < NB * IN0P; i += st) {
        int b = i >> 8, k = i & 255;
        float v;
        if      (k < 64)  v = emb[sl[b] * 64 + k];
        else if (k < 128) v = emb[el[b] * 64 + (k - 64)];
        else if (k < 191) v = sc[b * 63 + (k - 128)];
        else if (k < 254) v = ec[b * 63 + (k - 191)];
        else              v = 0.f;
        g_x[i] = to_tf32(v);
    }
    for (int i = i0; i < NB * HH; i += st) {
        g_h0[0][i] = 0.f; g_h1[0][i] = 0.f; g_c0[i] = 0.f; g_c1[i] = 0.f;
    }
}

// ---------------- fused GEMM + LSTM-gates kernel ----------------
// Block tile: 128 batch rows x 32 hidden units x 4 gates (N=128 gate-cols).
// MODE 0: layer0  (pre = acc + x0[row, gate*512+j]); A = h0[p], K=512
// MODE 1: layer1  (pre = acc + bias1[gate*512+j]);   A = [h0_new | h1_old], K=1024
// MODE 2: x0 build (out = acc + bias0[col]);         A = padded x, K=256
constexpr int BM = 128, BH = 32, KT = 16, SA = 20;

template<int MODE>
__global__ void __launch_bounds__(256, 2) gemm_gates_kernel(
    const float* __restrict__ A1, const float* __restrict__ A2,
    int lda, int K,
    const float* __restrict__ Wt,     // rows n = gate*512 + j, row stride K
    const float* __restrict__ addv,   // MODE0: x0[B][2048]; MODE1/2: bias[2048]
    float* __restrict__ cbuf,
    float* __restrict__ hout)         // MODE0/1: h[B][512]; MODE2: x0[B][2048]
{
    __shared__ float As[2][BM * SA];
    __shared__ float Bs[2][4 * BH * SA];

    const int tid  = threadIdx.x;
    const int lane = tid & 31;
    const int warp = tid >> 5;
    const int m0 = blockIdx.x * BM;
    const int j0 = blockIdx.y * BH;

    float acc[4][4][4];
#pragma unroll
    for (int g = 0; g < 4; ++g)
#pragma unroll
        for (int n = 0; n < 4; ++n)
#pragma unroll
            for (int c = 0; c < 4; ++c) acc[g][n][c] = 0.f;

    const int arow = tid >> 2;          // 0..63 (second chunk +64)
    const int ac4  = (tid & 3) * 4;

    auto ldg_tile = [&](int k0, float4& a0v, float4& a1v, float4& b0v, float4& b1v) {
        const float* Ab = A1; int kk = k0;
        if (MODE == 1 && k0 >= HH) { Ab = A2; kk = k0 - HH; }
        a0v = *reinterpret_cast<const float4*>(&Ab[(size_t)(m0 + arow)      * lda + kk + ac4]);
        a1v = *reinterpret_cast<const float4*>(&Ab[(size_t)(m0 + arow + 64) * lda + kk + ac4]);
        int g0 = arow >> 5,        jj0 = arow & 31;
        int g1 = (arow + 64) >> 5, jj1 = (arow + 64) & 31;
        b0v = *reinterpret_cast<const float4*>(&Wt[(size_t)(g0 * HH + j0 + jj0) * K + k0 + ac4]);
        b1v = *reinterpret_cast<const float4*>(&Wt[(size_t)(g1 * HH + j0 + jj1) * K + k0 + ac4]);
    };
    auto sts_tile = [&](int buf, const float4& a0v, const float4& a1v,
                        const float4& b0v, const float4& b1v) {
        *reinterpret_cast<float4*>(&As[buf][arow * SA + ac4])        = a0v;
        *reinterpret_cast<float4*>(&As[buf][(arow + 64) * SA + ac4]) = a1v;
        *reinterpret_cast<float4*>(&Bs[buf][arow * SA + ac4])        = b0v;
        *reinterpret_cast<float4*>(&Bs[buf][(arow + 64) * SA + ac4]) = b1v;
    };

    {
        float4 a0v, a1v, b0v, b1v;
        ldg_tile(0, a0v, a1v, b0v, b1v);
        sts_tile(0, a0v, a1v, b0v, b1v);
    }
    __syncthreads();

    const int NK = K / KT;
    int buf = 0;
    const int fr = warp * 16 + (lane >> 2);
    const int fk = lane & 3;
    const int bnq = lane >> 2;

    for (int kt = 0; kt < NK; ++kt) {
        float4 a0v, a1v, b0v, b1v;
        const bool pf = (kt + 1 < NK);
        if (pf) ldg_tile((kt + 1) * KT, a0v, a1v, b0v, b1v);

#pragma unroll
        for (int ks = 0; ks < 2; ++ks) {
            uint32_t fa0 = __float_as_uint(As[buf][fr * SA + fk + ks * 8]);
            uint32_t fa1 = __float_as_uint(As[buf][(fr + 8) * SA + fk + ks * 8]);
            uint32_t fa2 = __float_as_uint(As[buf][fr * SA + fk + 4 + ks * 8]);
            uint32_t fa3 = __float_as_uint(As[buf][(fr + 8) * SA + fk + 4 + ks * 8]);
#pragma unroll
            for (int g = 0; g < 4; ++g) {
#pragma unroll
                for (int nt = 0; nt < 4; ++nt) {
                    int bn = g * BH + nt * 8 + bnq;
                    uint32_t fb0 = __float_as_uint(Bs[buf][bn * SA + fk + ks * 8]);
                    uint32_t fb1 = __float_as_uint(Bs[buf][bn * SA + fk + 4 + ks * 8]);
                    mma_tf32(acc[g][nt], fa0, fa1, fa2, fa3, fb0, fb1);
                }
            }
        }
        if (pf) sts_tile(buf ^ 1, a0v, a1v, b0v, b1v);
        buf ^= 1;
        __syncthreads();
    }

    // epilogue
    const int r0 = m0 + warp * 16 + (lane >> 2);
    const int cb = j0 + (lane & 3) * 2;

    if (MODE == 2) {
#pragma unroll
        for (int g = 0; g < 4; ++g)
#pragma unroll
            for (int nt = 0; nt < 4; ++nt)
#pragma unroll
                for (int rr = 0; rr < 2; ++rr)
#pragma unroll
                    for (int e = 0; e < 2; ++e) {
                        int row = r0 + rr * 8;
                        int col = g * HH + cb + nt * 8 + e;
                        hout[(size_t)row * G4 + col] = acc[g][nt][rr * 2 + e] + addv[col];
                    }
    } else {
#pragma unroll
        for (int nt = 0; nt < 4; ++nt)
#pragma unroll
            for (int rr = 0; rr < 2; ++rr)
#pragma unroll
                for (int e = 0; e < 2; ++e) {
                    int row = r0 + rr * 8;
                    int jg  = cb + nt * 8 + e;
                    float pi = acc[0][nt][rr * 2 + e];
                    float pf_ = acc[1][nt][rr * 2 + e];
                    float pg = acc[2][nt][rr * 2 + e];
                    float po = acc[3][nt][rr * 2 + e];
                    if (MODE == 0) {
                        const float* xr = addv + (size_t)row * G4;
                        pi += xr[jg]; pf_ += xr[HH + jg];
                        pg += xr[2 * HH + jg]; po += xr[3 * HH + jg];
                    } else {
                        pi += addv[jg]; pf_ += addv[HH + jg];
                        pg += addv[2 * HH + jg]; po += addv[3 * HH + jg];
                    }
                    float co = cbuf[(size_t)row * HH + jg];
                    float cn = sigm(pf_) * co + sigm(pi) * tanhf(pg);
                    cbuf[(size_t)row * HH + jg] = cn;
                    hout[(size_t)row * HH + jg] = to_tf32(sigm(po) * tanhf(cn));
                }
    }
}

// ---------------- fc head: y = h1 @ fcW^T + fcb, coalesced [t][b][j] ----------------
__global__ void fc_kernel(const float* __restrict__ h1, const float* __restrict__ fcW,
                          const float* __restrict__ fcb, float* __restrict__ yout)
{
    __shared__ float sh[64 * 33];
    __shared__ float sw[64 * 33];
    const int tid = threadIdx.x;
    const int r0  = blockIdx.x * 64;
    const int rs  = tid & 15;
    const int cg  = tid >> 4;   // 0..15

    float acc[4][4];
#pragma unroll
    for (int r = 0; r < 4; ++r)
#pragma unroll
        for (int c = 0; c < 4; ++c) acc[r][c] = 0.f;

    for (int k0 = 0; k0 < HH; k0 += 32) {
        for (int q = tid; q < 512; q += 256) {
            int rr = q >> 3, c4 = (q & 7) * 4;
            float4 v = *reinterpret_cast<const float4*>(&h1[(size_t)(r0 + rr) * HH + k0 + c4]);
            sh[rr * 33 + c4 + 0] = v.x; sh[rr * 33 + c4 + 1] = v.y;
            sh[rr * 33 + c4 + 2] = v.z; sh[rr * 33 + c4 + 3] = v.w;
        }
        for (int q = tid; q < 64 * 32; q += 256) {
            int j = q >> 5, kk = q & 31;
            sw[j * 33 + kk] = (j < NJ) ? fcW[(size_t)j * HH + k0 + kk] : 0.f;
        }
        __syncthreads();
#pragma unroll
        for (int kk = 0; kk < 32; ++kk) {
            float hv[4], wv[4];
#pragma unroll
            for (int r = 0; r < 4; ++r) hv[r] = sh[(rs + r * 16) * 33 + kk];
#pragma unroll
            for (int c = 0; c < 4; ++c) wv[c] = sw[(cg * 4 + c) * 33 + kk];
#pragma unroll
            for (int r = 0; r < 4; ++r)
#pragma unroll
                for (int c = 0; c < 4; ++c) acc[r][c] += hv[r] * wv[c];
        }
        __syncthreads();
    }
#pragma unroll
    for (int r = 0; r < 4; ++r)
#pragma unroll
        for (int c = 0; c < 4; ++c) {
            int jj = cg * 4 + c;
            if (jj < NJ)
                yout[(size_t)(r0 + rs + r * 16) * NJ + jj] = acc[r][c] + fcb[jj];
        }
}

// ---------------- final transpose: [t][b][j] -> out[b][j][t] ----------------
__global__ void transpose_y(const float* __restrict__ gy, float* __restrict__ out)
{
    __shared__ float sy[NSEQ * NJ];
    const int b = blockIdx.x;
    for (int q = threadIdx.x; q < NSEQ * NJ; q += blockDim.x) {
        sy[q] = gy[(size_t)(q / NJ) * NB * NJ + (size_t)b * NJ + (q % NJ)];
    }
    __syncthreads();
    for (int q = threadIdx.x; q < NSEQ * NJ; q += blockDim.x) {
        int j = q / NSEQ, t = q - j * NSEQ;
        out[(size_t)b * (NJ * NSEQ) + q] = sy[t * NJ + j];
    }
}

// ---------------- host ----------------
template <typename T>
static float* symaddr(T& sym) {
    void* p = nullptr;
    cudaGetSymbolAddress(&p, sym);
    return (float*)p;
}

extern "C" void kernel_launch(void* const* d_in, const int* in_sizes, int n_in,
                              void* d_out, int out_size)
{
    const int*   sl   = (const int*)  d_in[0];
    const int*   el   = (const int*)  d_in[1];
    const float* sc   = (const float*)d_in[2];
    const float* ec   = (const float*)d_in[3];
    const float* emb  = (const float*)d_in[4];
    const float* Wih0 = (const float*)d_in[5];
    const float* Whh0 = (const float*)d_in[6];
    const float* bih0 = (const float*)d_in[7];
    const float* bhh0 = (const float*)d_in[8];
    const float* Wih1 = (const float*)d_in[9];
    const float* Whh1 = (const float*)d_in[10];
    const float* bih1 = (const float*)d_in[11];
    const float* bhh1 = (const float*)d_in[12];
    const float* fcW  = (const float*)d_in[13];
    const float* fcb  = (const float*)d_in[14];
    float* out = (float*)d_out;

    float* p_x    = symaddr(g_x);
    float* p_x0   = symaddr(g_x0);
    float* p_h0   = symaddr(g_h0);
    float* p_h1   = symaddr(g_h1);
    float* p_c0   = symaddr(g_c0);
    float* p_c1   = symaddr(g_c1);
    float* p_Wih0 = symaddr(g_Wih0);
    float* p_Whh0 = symaddr(g_Whh0);
    float* p_W1   = symaddr(g_W1);
    float* p_b0   = symaddr(g_bias0);
    float* p_b1   = symaddr(g_bias1);
    float* p_y    = symaddr(g_y);

    prep_weights_kernel<<<256, 256>>>(Wih0, Whh0, bih0, bhh0, Wih1, Whh1, bih1, bhh1);
    build_x_init_kernel<<<256, 256>>>(sl, el, sc, ec, emb);

    dim3 gg(NB / BM, HH / BH); // 32 x 16
    gemm_gates_kernel<2><<<gg, 256>>>(p_x, nullptr, IN0P, IN0P, p_Wih0, p_b0, nullptr, p_x0);

    for (int t = 0; t < NSEQ; ++t) {
        int p = t & 1;
        gemm_gates_kernel<0><<<gg, 256>>>(p_h0 + (size_t)p * NB * HH, nullptr, HH, HH,
                                          p_Whh0, p_x0, p_c0,
                                          p_h0 + (size_t)(p ^ 1) * NB * HH);
        gemm_gates_kernel<1><<<gg, 256>>>(p_h0 + (size_t)(p ^ 1) * NB * HH,
                                          p_h1 + (size_t)p * NB * HH, HH, 2 * HH,
                                          p_W1, p_b1, p_c1,
                                          p_h1 + (size_t)(p ^ 1) * NB * HH);
        fc_kernel<<<64, 256>>>(p_h1 + (size_t)(p ^ 1) * NB * HH, fcW, fcb,
                               p_y + (size_t)t * NB * NJ);
    }
    transpose_y<<<NB, 256>>>(p_y, out);
}

// round 2
// speedup vs baseline: 1.0017x; 1.0017x over previous
#include <cuda_runtime.h>
#include <cstdint>
#include <cstddef>

#define NB   4096
#define HH   512
#define G4   2048
#define NSEQ 100
#define NJ   63
#define IN0  254
#define IN0P 256

// ---------------- device scratch (no allocations allowed) ----------------
__device__ float g_x   [NB * IN0P];            // padded combined input (tf32-rounded)
__device__ float g_x0  [NB * G4];              // x @ W_ih0^T + b_ih0 + b_hh0
__device__ float g_h0  [2][NB * HH];           // ping-pong h0 (tf32-rounded)
__device__ float g_h1  [2][NB * HH];           // ping-pong h1 (tf32-rounded)
__device__ float g_c0  [NB * HH];
__device__ float g_c1  [NB * HH];
__device__ float g_Wih0[G4 * IN0P];            // tf32-rounded, K padded to 256
__device__ float g_Whh0[G4 * HH];              // tf32-rounded
__device__ float g_W1  [G4 * 2 * HH];          // [W_ih1 | W_hh1], tf32-rounded
__device__ float g_bias0[G4];                  // b_ih0 + b_hh0
__device__ float g_bias1[G4];                  // b_ih1 + b_hh1
__device__ float g_y   [(size_t)NSEQ * NB * NJ]; // staging [t][b][j]

// ---------------- helpers ----------------
__device__ __forceinline__ float to_tf32(float x) {
    uint32_t u;
    asm("cvt.rna.tf32.f32 %0, %1;" : "=r"(u) : "f"(x));
    return __uint_as_float(u);
}
__device__ __forceinline__ float sigm(float x) { return 1.f / (1.f + expf(-x)); }

__device__ __forceinline__ void mma_tf32(float (&c)[4],
    uint32_t a0, uint32_t a1, uint32_t a2, uint32_t a3, uint32_t b0, uint32_t b1)
{
    asm volatile(
        "mma.sync.aligned.m16n8k8.row.col.f32.tf32.tf32.f32 "
        "{%0,%1,%2,%3}, {%4,%5,%6,%7}, {%8,%9}, {%0,%1,%2,%3};\n"
        : "+f"(c[0]), "+f"(c[1]), "+f"(c[2]), "+f"(c[3])
        : "r"(a0), "r"(a1), "r"(a2), "r"(a3), "r"(b0), "r"(b1));
}

// ---------------- prologue kernels ----------------
__global__ void prep_weights_kernel(
    const float* __restrict__ Wih0, const float* __restrict__ Whh0,
    const float* __restrict__ bih0, const float* __restrict__ bhh0,
    const float* __restrict__ Wih1, const float* __restrict__ Whh1,
    const float* __restrict__ bih1, const float* __restrict__ bhh1)
{
    int i0 = blockIdx.x * blockDim.x + threadIdx.x;
    int st = gridDim.x * blockDim.x;
    for (int i = i0; i < G4 * IN0P; i += st) {
        int n = i >> 8, k = i & 255;
        g_Wih0[i] = (k < IN0) ? to_tf32(Wih0[n * IN0 + k]) : 0.f;
    }
    for (int i = i0; i < G4 * HH; i += st) g_Whh0[i] = to_tf32(Whh0[i]);
    for (int i = i0; i < G4 * 2 * HH; i += st) {
        int n = i >> 10, k = i & 1023;
        g_W1[i] = to_tf32(k < HH ? Wih1[n * HH + k] : Whh1[n * HH + k - HH]);
    }
    for (int i = i0; i < G4; i += st) {
        g_bias0[i] = bih0[i] + bhh0[i];
        g_bias1[i] = bih1[i] + bhh1[i];
    }
}

__global__ void build_x_init_kernel(
    const int* __restrict__ sl, const int* __restrict__ el,
    const float* __restrict__ sc, const float* __restrict__ ec,
    const float* __restrict__ emb)
{
    int i0 = blockIdx.x * blockDim.x + threadIdx.x;
    int st = gridDim.x * blockDim.x;
    for (int i = i0; i < NB * IN0P; i += st) {
        int b = i >> 8, k = i & 255;
        float v;
        if      (k < 64)  v = emb[sl[b] * 64 + k];
        else if (k < 128) v = emb[el[b] * 64 + (k - 64)];
        else if (k < 191) v = sc[b * 63 + (k - 128)];
        else if (k < 254) v = ec[b * 63 + (k - 191)];
        else              v = 0.f;
        g_x[i] = to_tf32(v);
    }
    for (int i = i0; i < NB * HH; i += st) {
        g_h0[0][i] = 0.f; g_h1[0][i] = 0.f; g_c0[i] = 0.f; g_c1[i] = 0.f;
    }
}

// ---------------- fused GEMM + LSTM-gates kernel ----------------
// Block tile: 128 batch rows x 32 hidden units x 4 gates (N=128 gate-cols).
// MODE 0: layer0  (pre = acc + x0[row, gate*512+j]); A = h0[p], K=512
// MODE 1: layer1  (pre = acc + bias1[gate*512+j]);   A = [h0_new | h1_old], K=1024
// MODE 2: x0 build (out = acc + bias0[col]);         A = padded x, K=256
constexpr int BM = 128, BH = 32, KT = 16, SA = 20;

template<int MODE>
__global__ void __launch_bounds__(256, 2) gemm_gates_kernel(
    const float* __restrict__ A1, const float* __restrict__ A2,
    int lda, int K,
    const float* __restrict__ Wt,     // rows n = gate*512 + j, row stride K
    const float* __restrict__ addv,   // MODE0: x0[B][2048]; MODE1/2: bias[2048]
    float* __restrict__ cbuf,
    float* __restrict__ hout)         // MODE0/1: h[B][512]; MODE2: x0[B][2048]
{
    __shared__ float As[2][BM * SA];
    __shared__ float Bs[2][4 * BH * SA];

    const int tid  = threadIdx.x;
    const int lane = tid & 31;
    const int warp = tid >> 5;
    const int m0 = blockIdx.x * BM;
    const int j0 = blockIdx.y * BH;

    float acc[4][4][4];
#pragma unroll
    for (int g = 0; g < 4; ++g)
#pragma unroll
        for (int n = 0; n < 4; ++n)
#pragma unroll
            for (int c = 0; c < 4; ++c) acc[g][n][c] = 0.f;

    const int arow = tid >> 2;          // 0..63 (second chunk +64)
    const int ac4  = (tid & 3) * 4;

    auto ldg_tile = [&](int k0, float4& a0v, float4& a1v, float4& b0v, float4& b1v) {
        const float* Ab = A1; int kk = k0;
        if (MODE == 1 && k0 >= HH) { Ab = A2; kk = k0 - HH; }
        a0v = *reinterpret_cast<const float4*>(&Ab[(size_t)(m0 + arow)      * lda + kk + ac4]);
        a1v = *reinterpret_cast<const float4*>(&Ab[(size_t)(m0 + arow + 64) * lda + kk + ac4]);
        int g0 = arow >> 5,        jj0 = arow & 31;
        int g1 = (arow + 64) >> 5, jj1 = (arow + 64) & 31;
        b0v = *reinterpret_cast<const float4*>(&Wt[(size_t)(g0 * HH + j0 + jj0) * K + k0 + ac4]);
        b1v = *reinterpret_cast<const float4*>(&Wt[(size_t)(g1 * HH + j0 + jj1) * K + k0 + ac4]);
    };
    auto sts_tile = [&](int buf, const float4& a0v, const float4& a1v,
                        const float4& b0v, const float4& b1v) {
        *reinterpret_cast<float4*>(&As[buf][arow * SA + ac4])        = a0v;
        *reinterpret_cast<float4*>(&As[buf][(arow + 64) * SA + ac4]) = a1v;
        *reinterpret_cast<float4*>(&Bs[buf][arow * SA + ac4])        = b0v;
        *reinterpret_cast<float4*>(&Bs[buf][(arow + 64) * SA + ac4]) = b1v;
    };

    {
        float4 a0v, a1v, b0v, b1v;
        ldg_tile(0, a0v, a1v, b0v, b1v);
        sts_tile(0, a0v, a1v, b0v, b1v);
    }
    __syncthreads();

    const int NK = K / KT;
    int buf = 0;
    const int fr = warp * 16 + (lane >> 2);
    const int fk = lane & 3;
    const int bnq = lane >> 2;

    for (int kt = 0; kt < NK; ++kt) {
        float4 a0v, a1v, b0v, b1v;
        const bool pf = (kt + 1 < NK);
        if (pf) ldg_tile((kt + 1) * KT, a0v, a1v, b0v, b1v);

#pragma unroll
        for (int ks = 0; ks < 2; ++ks) {
            uint32_t fa0 = __float_as_uint(As[buf][fr * SA + fk + ks * 8]);
            uint32_t fa1 = __float_as_uint(As[buf][(fr + 8) * SA + fk + ks * 8]);
            uint32_t fa2 = __float_as_uint(As[buf][fr * SA + fk + 4 + ks * 8]);
            uint32_t fa3 = __float_as_uint(As[buf][(fr + 8) * SA + fk + 4 + ks * 8]);
#pragma unroll
            for (int g = 0; g < 4; ++g) {
#pragma unroll
                for (int nt = 0; nt < 4; ++nt) {
                    int bn = g * BH + nt * 8 + bnq;
                    uint32_t fb0 = __float_as_uint(Bs[buf][bn * SA + fk + ks * 8]);
                    uint32_t fb1 = __float_as_uint(Bs[buf][bn * SA + fk + 4 + ks * 8]);
                    mma_tf32(acc[g][nt], fa0, fa1, fa2, fa3, fb0, fb1);
                }
            }
        }
        if (pf) sts_tile(buf ^ 1, a0v, a1v, b0v, b1v);
        buf ^= 1;
        __syncthreads();
    }

    // epilogue
    const int r0 = m0 + warp * 16 + (lane >> 2);
    const int cb = j0 + (lane & 3) * 2;

    if (MODE == 2) {
#pragma unroll
        for (int g = 0; g < 4; ++g)
#pragma unroll
            for (int nt = 0; nt < 4; ++nt)
#pragma unroll
                for (int rr = 0; rr < 2; ++rr)
#pragma unroll
                    for (int e = 0; e < 2; ++e) {
                        int row = r0 + rr * 8;
                        int col = g * HH + cb + nt * 8 + e;
                        hout[(size_t)row * G4 + col] = acc[g][nt][rr * 2 + e] + addv[col];
                    }
    } else {
#pragma unroll
        for (int nt = 0; nt < 4; ++nt)
#pragma unroll
            for (int rr = 0; rr < 2; ++rr)
#pragma unroll
                for (int e = 0; e < 2; ++e) {
                    int row = r0 + rr * 8;
                    int jg  = cb + nt * 8 + e;
                    float pi = acc[0][nt][rr * 2 + e];
                    float pf_ = acc[1][nt][rr * 2 + e];
                    float pg = acc[2][nt][rr * 2 + e];
                    float po = acc[3][nt][rr * 2 + e];
                    if (MODE == 0) {
                        const float* xr = addv + (size_t)row * G4;
                        pi += xr[jg]; pf_ += xr[HH + jg];
                        pg += xr[2 * HH + jg]; po += xr[3 * HH + jg];
                    } else {
                        pi += addv[jg]; pf_ += addv[HH + jg];
                        pg += addv[2 * HH + jg]; po += addv[3 * HH + jg];
                    }
                    float co = cbuf[(size_t)row * HH + jg];
                    float cn = sigm(pf_) * co + sigm(pi) * tanhf(pg);
                    cbuf[(size_t)row * HH + jg] = cn;
                    hout[(size_t)row * HH + jg] = to_tf32(sigm(po) * tanhf(cn));
                }
    }
}

// ---------------- fc head: y = h1 @ fcW^T + fcb, coalesced [t][b][j] ----------------
__global__ void fc_kernel(const float* __restrict__ h1, const float* __restrict__ fcW,
                          const float* __restrict__ fcb, float* __restrict__ yout)
{
    __shared__ float sh[64 * 33];
    __shared__ float sw[64 * 33];
    const int tid = threadIdx.x;
    const int r0  = blockIdx.x * 64;
    const int rs  = tid & 15;
    const int cg  = tid >> 4;   // 0..15

    float acc[4][4];
#pragma unroll
    for (int r = 0; r < 4; ++r)
#pragma unroll
        for (int c = 0; c < 4; ++c) acc[r][c] = 0.f;

    for (int k0 = 0; k0 < HH; k0 += 32) {
        for (int q = tid; q < 512; q += 256) {
            int rr = q >> 3, c4 = (q & 7) * 4;
            float4 v = *reinterpret_cast<const float4*>(&h1[(size_t)(r0 + rr) * HH + k0 + c4]);
            sh[rr * 33 + c4 + 0] = v.x; sh[rr * 33 + c4 + 1] = v.y;
            sh[rr * 33 + c4 + 2] = v.z; sh[rr * 33 + c4 + 3] = v.w;
        }
        for (int q = tid; q < 64 * 32; q += 256) {
            int j = q >> 5, kk = q & 31;
            sw[j * 33 + kk] = (j < NJ) ? fcW[(size_t)j * HH + k0 + kk] : 0.f;
        }
        __syncthreads();
#pragma unroll
        for (int kk = 0; kk < 32; ++kk) {
            float hv[4], wv[4];
#pragma unroll
            for (int r = 0; r < 4; ++r) hv[r] = sh[(rs + r * 16) * 33 + kk];
#pragma unroll
            for (int c = 0; c < 4; ++c) wv[c] = sw[(cg * 4 + c) * 33 + kk];
#pragma unroll
            for (int r = 0; r < 4; ++r)
#pragma unroll
                for (int c = 0; c < 4; ++c) acc[r][c] += hv[r] * wv[c];
        }
        __syncthreads();
    }
#pragma unroll
    for (int r = 0; r < 4; ++r)
#pragma unroll
        for (int c = 0; c < 4; ++c) {
            int jj = cg * 4 + c;
            if (jj < NJ)
                yout[(size_t)(r0 + rs + r * 16) * NJ + jj] = acc[r][c] + fcb[jj];
        }
}

// ---------------- final transpose: [t][b][j] -> out[b][j][t] ----------------
__global__ void transpose_y(const float* __restrict__ gy, float* __restrict__ out)
{
    __shared__ float sy[NSEQ * NJ];
    const int b = blockIdx.x;
    for (int q = threadIdx.x; q < NSEQ * NJ; q += blockDim.x) {
        sy[q] = gy[(size_t)(q / NJ) * NB * NJ + (size_t)b * NJ + (q % NJ)];
    }
    __syncthreads();
    for (int q = threadIdx.x; q < NSEQ * NJ; q += blockDim.x) {
        int j = q / NSEQ, t = q - j * NSEQ;
        out[(size_t)b * (NJ * NSEQ) + q] = sy[t * NJ + j];
    }
}

// ---------------- host ----------------
template <typename T>
static float* symaddr(T& sym) {
    void* p = nullptr;
    cudaGetSymbolAddress(&p, sym);
    return (float*)p;
}

extern "C" void kernel_launch(void* const* d_in, const int* in_sizes, int n_in,
                              void* d_out, int out_size)
{
    const int*   sl   = (const int*)  d_in[0];
    const int*   el   = (const int*)  d_in[1];
    const float* sc   = (const float*)d_in[2];
    const float* ec   = (const float*)d_in[3];
    const float* emb  = (const float*)d_in[4];
    const float* Wih0 = (const float*)d_in[5];
    const float* Whh0 = (const float*)d_in[6];
    const float* bih0 = (const float*)d_in[7];
    const float* bhh0 = (const float*)d_in[8];
    const float* Wih1 = (const float*)d_in[9];
    const float* Whh1 = (const float*)d_in[10];
    const float* bih1 = (const float*)d_in[11];
    const float* bhh1 = (const float*)d_in[12];
    const float* fcW  = (const float*)d_in[13];
    const float* fcb  = (const float*)d_in[14];
    float* out = (float*)d_out;

    float* p_x    = symaddr(g_x);
    float* p_x0   = symaddr(g_x0);
    float* p_h0   = symaddr(g_h0);
    float* p_h1   = symaddr(g_h1);
    float* p_c0   = symaddr(g_c0);
    float* p_c1   = symaddr(g_c1);
    float* p_Wih0 = symaddr(g_Wih0);
    float* p_Whh0 = symaddr(g_Whh0);
    float* p_W1   = symaddr(g_W1);
    float* p_b0   = symaddr(g_bias0);
    float* p_b1   = symaddr(g_bias1);
    float* p_y    = symaddr(g_y);

    prep_weights_kernel<<<256, 256>>>(Wih0, Whh0, bih0, bhh0, Wih1, Whh1, bih1, bhh1);
    build_x_init_kernel<<<256, 256>>>(sl, el, sc, ec, emb);

    dim3 gg(NB / BM, HH / BH); // 32 x 16
    gemm_gates_kernel<2><<<gg, 256>>>(p_x, nullptr, IN0P, IN0P, p_Wih0, p_b0, nullptr, p_x0);

    for (int t = 0; t < NSEQ; ++t) {
        int p = t & 1;
        gemm_gates_kernel<0><<<gg, 256>>>(p_h0 + (size_t)p * NB * HH, nullptr, HH, HH,
                                          p_Whh0, p_x0, p_c0,
                                          p_h0 + (size_t)(p ^ 1) * NB * HH);
        gemm_gates_kernel<1><<<gg, 256>>>(p_h0 + (size_t)(p ^ 1) * NB * HH,
                                          p_h1 + (size_t)p * NB * HH, HH, 2 * HH,
                                          p_W1, p_b1, p_c1,
                                          p_h1 + (size_t)(p ^ 1) * NB * HH);
        fc_kernel<<<64, 256>>>(p_h1 + (size_t)(p ^ 1) * NB * HH, fcW, fcb,
                               p_y + (size_t)t * NB * NJ);
    }
    transpose_y<<<NB, 256>>>(p_y, out);
}

// round 4
// speedup vs baseline: 2.4125x; 2.4083x over previous
#include <cuda_runtime.h>
#include <cuda_fp16.h>
#include <cstdint>
#include <cstddef>

#define NB 4096
#define HH 512
#define NSEQ 100
#define NJ 63

// ---------- device scratch ----------
__device__ __align__(1024) __half g_xh [NB * 256];
__device__ __align__(1024) __half g_h0h[2][NB * HH];
__device__ __align__(1024) __half g_h1h[2][NB * HH];
__device__ __align__(1024) float  g_c0 [NB * HH];
__device__ __align__(1024) float  g_c1 [NB * HH];
__device__ __align__(1024) __half g_Wi0p[16 * 128 * 256];
__device__ __align__(1024) __half g_Wp0 [16 * 128 * 512];
__device__ __align__(1024) __half g_Wp1 [16 * 128 * 1024];
__device__ float g_b0p[2048];
__device__ float g_b1p[2048];
__device__ __align__(1024) float g_x0T[(size_t)2048 * NB];  // [packed n][b]
__device__ float g_y[(size_t)NSEQ * NB * NJ];

// ---------- helpers ----------
__device__ __forceinline__ float sigm(float x) { return 1.f / (1.f + expf(-x)); }
__device__ __forceinline__ uint32_t smem_u32(const void* p) {
    uint32_t a;
    asm("{ .reg .u64 t; cvta.to.shared.u64 t, %1; cvt.u32.u64 %0, t; }" : "=r"(a) : "l"(p));
    return a;
}

#define CP16(dst, src) asm volatile("cp.async.cg.shared.global [%0], [%1], 16;" :: "r"((uint32_t)(dst)), "l"(src) : "memory")
#define CP_COMMIT()    asm volatile("cp.async.commit_group;" ::: "memory")
#define CP_WAIT(n)     asm volatile("cp.async.wait_group %0;" :: "n"(n) : "memory")

#define LDSM_X4(r0, r1, r2, r3, a) \
    asm volatile("ldmatrix.sync.aligned.m8n8.x4.shared.b16 {%0,%1,%2,%3}, [%4];" \
        : "=r"(r0), "=r"(r1), "=r"(r2), "=r"(r3) : "r"(a))

__device__ __forceinline__ void hmma(float (&c)[4],
    uint32_t a0, uint32_t a1, uint32_t a2, uint32_t a3, uint32_t b0, uint32_t b1)
{
    asm volatile(
        "mma.sync.aligned.m16n8k16.row.col.f32.f16.f16.f32 "
        "{%0,%1,%2,%3}, {%4,%5,%6,%7}, {%8,%9}, {%0,%1,%2,%3};\n"
        : "+f"(c[0]), "+f"(c[1]), "+f"(c[2]), "+f"(c[3])
        : "r"(a0), "r"(a1), "r"(a2), "r"(a3), "r"(b0), "r"(b1));
}

__device__ __forceinline__ uint32_t sw128(uint32_t off) {
    return off ^ ((off >> 3) & 0x70);
}

// ---------- prologue ----------
// Packed weights: g_Wp[jt][n][k], n = g*32 + u  ->  original row g*512 + jt*32 + u
__global__ void pack_weights(
    const float* __restrict__ Wih0, const float* __restrict__ Whh0,
    const float* __restrict__ bih0, const float* __restrict__ bhh0,
    const float* __restrict__ Wih1, const float* __restrict__ Whh1,
    const float* __restrict__ bih1, const float* __restrict__ bhh1)
{
    int i0 = blockIdx.x * blockDim.x + threadIdx.x;
    int st = gridDim.x * blockDim.x;
    for (int i = i0; i < 16 * 128 * 512; i += st) {
        int jt = i >> 16, n = (i >> 9) & 127, k = i & 511;
        int row = (n >> 5) * HH + jt * 32 + (n & 31);
        g_Wp0[i] = __float2half_rn(Whh0[(size_t)row * HH + k]);
    }
    for (int i = i0; i < 16 * 128 * 1024; i += st) {
        int jt = i >> 17, n = (i >> 10) & 127, k = i & 1023;
        int row = (n >> 5) * HH + jt * 32 + (n & 31);
        float v = (k < HH) ? Wih1[(size_t)row * HH + k] : Whh1[(size_t)row * HH + k - HH];
        g_Wp1[i] = __float2half_rn(v);
    }
    for (int i = i0; i < 16 * 128 * 256; i += st) {
        int jt = i >> 15, n = (i >> 8) & 127, k = i & 255;
        int row = (n >> 5) * HH + jt * 32 + (n & 31);
        g_Wi0p[i] = (k < 254) ? __float2half_rn(Wih0[(size_t)row * 254 + k]) : __half(0);
    }
    for (int i = i0; i < 2048; i += st) {
        int jt = i >> 7, n = i & 127;
        int row = (n >> 5) * HH + jt * 32 + (n & 31);
        g_b0p[i] = bih0[row] + bhh0[row];
        g_b1p[i] = bih1[row] + bhh1[row];
    }
}

__global__ void build_x_init(
    const int* __restrict__ sl, const int* __restrict__ el,
    const float* __restrict__ sc, const float* __restrict__ ec,
    const float* __restrict__ emb)
{
    int i0 = blockIdx.x * blockDim.x + threadIdx.x;
    int st = gridDim.x * blockDim.x;
    for (int i = i0; i < NB * 256; i += st) {
        int b = i >> 8, k = i & 255;
        float v;
        if      (k < 64)  v = emb[sl[b] * 64 + k];
        else if (k < 128) v = emb[el[b] * 64 + (k - 64)];
        else if (k < 191) v = sc[b * 63 + (k - 128)];
        else if (k < 254) v = ec[b * 63 + (k - 191)];
        else              v = 0.f;
        g_xh[i] = __float2half_rn(v);
    }
    __half z = __half(0);
    for (int i = i0; i < NB * HH; i += st) {
        g_h0h[0][i] = z; g_h1h[0][i] = z; g_c0[i] = 0.f; g_c1[i] = 0.f;
    }
}

// ---------- fused fp16 HMMA GEMM + LSTM gates ----------
// Block: 128 batch x 128 cols (4 gates x 32 units). 8 warps, warp = 16 rows x 128 cols.
// K chunk 64 halves (128B rows, SW128), 2-stage cp.async double buffer.
// MODE 0: layer0 (K=512, add x0T)   MODE 1: layer1 (K=1024, add bias1)
// MODE 2: x0 build (K=256, add bias0, out x0T transposed)
constexpr int STGB = 32768;                // A 16KB + B 16KB
constexpr int SMEMSZ = 2 * STGB;           // 64 KB

template<int MODE>
__global__ void __launch_bounds__(256, 2) gemm_step(
    const __half* __restrict__ A1, const __half* __restrict__ A2,
    const __half* __restrict__ Wp, const float* __restrict__ addv,
    float* __restrict__ cbuf, void* __restrict__ houtv)
{
    extern __shared__ char smem[];
    const uint32_t sb = smem_u32(smem);
    const int tid = threadIdx.x, wid = tid >> 5, lane = tid & 31;
    const int m0 = blockIdx.x * 128, jt = blockIdx.y;
    constexpr int KW  = (MODE == 0) ? 512 : (MODE == 1) ? 1024 : 256;
    constexpr int LDA = (MODE == 2) ? 256 : 512;
    constexpr int NT  = KW / 64;

    const __half* Bb = Wp + (size_t)jt * 128 * KW;

    auto copy_stage = [&](int s, int kt) {
        const uint32_t ab = sb + s * STGB, bbs = ab + 16384;
        const int k0 = kt * 64;
#pragma unroll
        for (int i = 0; i < 4; ++i) {
            int idx = tid + i * 256;
            int row = idx >> 3, ck = idx & 7;
            uint32_t sw = sw128(row * 128 + ck * 16);
            const __half* As = (MODE == 1 && k0 >= 512)
                ? A2 + (size_t)(m0 + row) * LDA + (k0 - 512) + ck * 8
                : A1 + (size_t)(m0 + row) * LDA + k0 + ck * 8;
            CP16(ab + sw, As);
            CP16(bbs + sw, Bb + (size_t)row * KW + k0 + ck * 8);
        }
    };

    float acc[4][4][4];
#pragma unroll
    for (int g = 0; g < 4; ++g)
#pragma unroll
        for (int n = 0; n < 4; ++n)
#pragma unroll
            for (int e = 0; e < 4; ++e) acc[g][n][e] = 0.f;

    copy_stage(0, 0);
    CP_COMMIT();

    const int q = lane >> 3, rr = lane & 7;
    const int arow = wid * 16 + (q & 1) * 8 + rr;     // A ldmatrix row
    const int akh  = (q >> 1) * 16;                   // A k-half byte offset
    const int bkh  = (q & 1) * 16;                    // B k-half byte offset
    const int brow = (q >> 1) * 8 + rr;               // B row within 16-group

    for (int kt = 0; kt < NT; ++kt) {
        if (kt + 1 < NT) {
            copy_stage((kt + 1) & 1, kt + 1);
            CP_COMMIT();
            CP_WAIT(1);
        } else {
            CP_WAIT(0);
        }
        __syncthreads();
        const uint32_t ab = sb + (kt & 1) * STGB, bbs = ab + 16384;
#pragma unroll
        for (int ks = 0; ks < 4; ++ks) {
            uint32_t a0, a1, a2, a3;
            LDSM_X4(a0, a1, a2, a3, ab + sw128(arow * 128 + ks * 32 + akh));
#pragma unroll
            for (int m = 0; m < 8; ++m) {
                uint32_t b0, b1, b2, b3;
                LDSM_X4(b0, b1, b2, b3,
                        bbs + sw128((m * 16 + brow) * 128 + ks * 32 + bkh));
                int gi = m * 2;
                hmma(acc[gi >> 2][gi & 3], a0, a1, a2, a3, b0, b1);
                gi = m * 2 + 1;
                hmma(acc[gi >> 2][gi & 3], a0, a1, a2, a3, b2, b3);
            }
        }
        __syncthreads();
    }

    // ---------- epilogue ----------
    const int r0 = m0 + wid * 16 + (lane >> 2);
    const int ub = (lane & 3) * 2;   // even unit base within 8-col group

    if (MODE == 2) {
        float* x0T = (float*)houtv;
#pragma unroll
        for (int g = 0; g < 4; ++g)
#pragma unroll
            for (int nt = 0; nt < 4; ++nt)
#pragma unroll
                for (int r = 0; r < 2; ++r)
#pragma unroll
                    for (int e = 0; e < 2; ++e) {
                        int n = jt * 128 + g * 32 + nt * 8 + ub + e;
                        x0T[(size_t)n * NB + r0 + r * 8] = acc[g][nt][r * 2 + e] + addv[n];
                    }
    } else {
        __half* hout = (__half*)houtv;
#pragma unroll
        for (int nt = 0; nt < 4; ++nt) {
            const int u = nt * 8 + ub;          // even, within 32-unit group
            const int n0 = jt * 32 + u;         // hidden index
#pragma unroll
            for (int r = 0; r < 2; ++r) {
                const int row = r0 + r * 8;
                float add[4][2];
                if (MODE == 0) {
#pragma unroll
                    for (int g = 0; g < 4; ++g) {
                        const float* xp = addv + (size_t)(jt * 128 + g * 32 + u) * NB + row;
                        add[g][0] = xp[0];
                        add[g][1] = xp[NB];
                    }
                } else {
#pragma unroll
                    for (int g = 0; g < 4; ++g) {
                        add[g][0] = addv[jt * 128 + g * 32 + u];
                        add[g][1] = addv[jt * 128 + g * 32 + u + 1];
                    }
                }
                float2 co = *reinterpret_cast<const float2*>(&cbuf[(size_t)row * HH + n0]);
                float cn[2], hn[2];
#pragma unroll
                for (int e = 0; e < 2; ++e) {
                    float pi = acc[0][nt][r * 2 + e] + add[0][e];
                    float pf = acc[1][nt][r * 2 + e] + add[1][e];
                    float pg = acc[2][nt][r * 2 + e] + add[2][e];
                    float po = acc[3][nt][r * 2 + e] + add[3][e];
                    float cold = e ? co.y : co.x;
                    float cv = sigm(pf) * cold + sigm(pi) * tanhf(pg);
                    cn[e] = cv;
                    hn[e] = sigm(po) * tanhf(cv);
                }
                *reinterpret_cast<float2*>(&cbuf[(size_t)row * HH + n0]) =
                    make_float2(cn[0], cn[1]);
                *reinterpret_cast<__half2*>(&hout[(size_t)row * HH + n0]) =
                    __floats2half2_rn(hn[0], hn[1]);
            }
        }
    }
}

// ---------- fc head (h1 fp16) ----------
__global__ void fc_kernel(const __half* __restrict__ h1, const float* __restrict__ fcW,
                          const float* __restrict__ fcb, float* __restrict__ yout)
{
    __shared__ float sh[64 * 33];
    __shared__ float sw[64 * 33];
    const int tid = threadIdx.x, r0 = blockIdx.x * 64;
    const int rs = tid & 15, cg = tid >> 4;
    float acc[4][4];
#pragma unroll
    for (int r = 0; r < 4; ++r)
#pragma unroll
        for (int c = 0; c < 4; ++c) acc[r][c] = 0.f;

    for (int k0 = 0; k0 < HH; k0 += 32) {
        {
            int rr = tid >> 2, seg = tid & 3;
            uint4 v = *reinterpret_cast<const uint4*>(&h1[(size_t)(r0 + rr) * HH + k0 + seg * 8]);
            const __half2* hp = reinterpret_cast<const __half2*>(&v);
            float* d = &sh[rr * 33 + seg * 8];
#pragma unroll
            for (int m = 0; m < 4; ++m) {
                float2 f = __half22float2(hp[m]);
                d[2 * m] = f.x; d[2 * m + 1] = f.y;
            }
        }
        for (int q2 = tid; q2 < 64 * 32; q2 += 256) {
            int j = q2 >> 5, kk = q2 & 31;
            sw[j * 33 + kk] = (j < NJ) ? fcW[(size_t)j * HH + k0 + kk] : 0.f;
        }
        __syncthreads();
#pragma unroll
        for (int kk = 0; kk < 32; ++kk) {
            float hv[4], wv[4];
#pragma unroll
            for (int r = 0; r < 4; ++r) hv[r] = sh[(rs + r * 16) * 33 + kk];
#pragma unroll
            for (int c = 0; c < 4; ++c) wv[c] = sw[(cg * 4 + c) * 33 + kk];
#pragma unroll
            for (int r = 0; r < 4; ++r)
#pragma unroll
                for (int c = 0; c < 4; ++c) acc[r][c] += hv[r] * wv[c];
        }
        __syncthreads();
    }
#pragma unroll
    for (int r = 0; r < 4; ++r)
#pragma unroll
        for (int c = 0; c < 4; ++c) {
            int jj = cg * 4 + c;
            if (jj < NJ)
                yout[(size_t)(r0 + rs + r * 16) * NJ + jj] = acc[r][c] + fcb[jj];
        }
}

// ---------- final transpose [t][b][j] -> [b][j][t] ----------
__global__ void transpose_y(const float* __restrict__ gy, float* __restrict__ out)
{
    __shared__ float sy[NSEQ * NJ];
    const int b = blockIdx.x;
    for (int q = threadIdx.x; q < NSEQ * NJ; q += blockDim.x)
        sy[q] = gy[(size_t)(q / NJ) * NB * NJ + (size_t)b * NJ + (q % NJ)];
    __syncthreads();
    for (int q = threadIdx.x; q < NSEQ * NJ; q += blockDim.x) {
        int j = q / NSEQ, t = q - j * NSEQ;
        out[(size_t)b * (NJ * NSEQ) + q] = sy[t * NJ + j];
    }
}

// ---------- host ----------
template <typename T>
static void* symaddr(T& sym) {
    void* p = nullptr;
    cudaGetSymbolAddress(&p, sym);
    return p;
}

extern "C" void kernel_launch(void* const* d_in, const int* in_sizes, int n_in,
                              void* d_out, int out_size)
{
    const int*   sl   = (const int*)  d_in[0];
    const int*   el   = (const int*)  d_in[1];
    const float* sc   = (const float*)d_in[2];
    const float* ec   = (const float*)d_in[3];
    const float* emb  = (const float*)d_in[4];
    const float* Wih0 = (const float*)d_in[5];
    const float* Whh0 = (const float*)d_in[6];
    const float* bih0 = (const float*)d_in[7];
    const float* bhh0 = (const float*)d_in[8];
    const float* Wih1 = (const float*)d_in[9];
    const float* Whh1 = (const float*)d_in[10];
    const float* bih1 = (const float*)d_in[11];
    const float* bhh1 = (const float*)d_in[12];
    const float* fcW  = (const float*)d_in[13];
    const float* fcb  = (const float*)d_in[14];
    float* out = (float*)d_out;

    __half* p_xh   = (__half*)symaddr(g_xh);
    __half* p_h0h  = (__half*)symaddr(g_h0h);
    __half* p_h1h  = (__half*)symaddr(g_h1h);
    float*  p_c0   = (float*) symaddr(g_c0);
    float*  p_c1   = (float*) symaddr(g_c1);
    __half* p_Wi0p = (__half*)symaddr(g_Wi0p);
    __half* p_Wp0  = (__half*)symaddr(g_Wp0);
    __half* p_Wp1  = (__half*)symaddr(g_Wp1);
    float*  p_b0p  = (float*) symaddr(g_b0p);
    float*  p_b1p  = (float*) symaddr(g_b1p);
    float*  p_x0T  = (float*) symaddr(g_x0T);
    float*  p_y    = (float*) symaddr(g_y);

    cudaFuncSetAttribute(gemm_step<0>, cudaFuncAttributeMaxDynamicSharedMemorySize, SMEMSZ);
    cudaFuncSetAttribute(gemm_step<1>, cudaFuncAttributeMaxDynamicSharedMemorySize, SMEMSZ);
    cudaFuncSetAttribute(gemm_step<2>, cudaFuncAttributeMaxDynamicSharedMemorySize, SMEMSZ);

    pack_weights<<<256, 256>>>(Wih0, Whh0, bih0, bhh0, Wih1, Whh1, bih1, bhh1);
    build_x_init<<<256, 256>>>(sl, el, sc, ec, emb);

    const dim3 gg(32, 16);
    const size_t NH = (size_t)NB * HH;
    gemm_step<2><<<gg, 256, SMEMSZ>>>(p_xh, nullptr, p_Wi0p, p_b0p, nullptr, p_x0T);

    for (int t = 0; t < NSEQ; ++t) {
        int p = t & 1;
        gemm_step<0><<<gg, 256, SMEMSZ>>>(p_h0h + p * NH, nullptr, p_Wp0, p_x0T,
                                          p_c0, p_h0h + (p ^ 1) * NH);
        gemm_step<1><<<gg, 256, SMEMSZ>>>(p_h0h + (p ^ 1) * NH, p_h1h + p * NH, p_Wp1, p_b1p,
                                          p_c1, p_h1h + (p ^ 1) * NH);
        fc_kernel<<<64, 256>>>(p_h1h + (p ^ 1) * NH, fcW, fcb, p_y + (size_t)t * NB * NJ);
    }
    transpose_y<<<NB, 256>>>(p_y, out);
}

// round 5
// speedup vs baseline: 2.4469x; 1.0143x over previous
#include <cuda_runtime.h>
#include <cuda_fp16.h>
#include <cstdint>
#include <cstddef>

#define NB 4096
#define HH 512
#define NSEQ 100
#define NJ 63

// ---------- device scratch ----------
__device__ __align__(1024) __half g_xh [NB * 256];
__device__ __align__(1024) __half g_h0h[2][NB * HH];
__device__ __align__(1024) __half g_h1a[(size_t)(NSEQ + 1) * NB * HH]; // h1 history
__device__ __align__(1024) float  g_c0 [NB * HH];
__device__ __align__(1024) float  g_c1 [NB * HH];
__device__ __align__(1024) __half g_Wi0p[16 * 128 * 256];
__device__ __align__(1024) __half g_Wp0 [16 * 128 * 512];
__device__ __align__(1024) __half g_Wp1 [16 * 128 * 1024];
__device__ float g_b0p[2048];
__device__ float g_b1p[2048];
__device__ __align__(1024) float g_x0T[(size_t)2048 * NB];  // [packed n][b]
__device__ float g_y[(size_t)NSEQ * NB * NJ];

// ---------- helpers ----------
__device__ __forceinline__ float sigm(float x) { return 1.f / (1.f + expf(-x)); }
__device__ __forceinline__ uint32_t smem_u32(const void* p) {
    uint32_t a;
    asm("{ .reg .u64 t; cvta.to.shared.u64 t, %1; cvt.u32.u64 %0, t; }" : "=r"(a) : "l"(p));
    return a;
}
#define CP16(dst, src) asm volatile("cp.async.cg.shared.global [%0], [%1], 16;" :: "r"((uint32_t)(dst)), "l"(src) : "memory")
#define CP_COMMIT()    asm volatile("cp.async.commit_group;" ::: "memory")
#define CP_WAIT(n)     asm volatile("cp.async.wait_group %0;" :: "n"(n) : "memory")
#define LDSM_X4(r0, r1, r2, r3, a) \
    asm volatile("ldmatrix.sync.aligned.m8n8.x4.shared.b16 {%0,%1,%2,%3}, [%4];" \
        : "=r"(r0), "=r"(r1), "=r"(r2), "=r"(r3) : "r"(a))

__device__ __forceinline__ void hmma(float (&c)[4],
    uint32_t a0, uint32_t a1, uint32_t a2, uint32_t a3, uint32_t b0, uint32_t b1)
{
    asm volatile(
        "mma.sync.aligned.m16n8k16.row.col.f32.f16.f16.f32 "
        "{%0,%1,%2,%3}, {%4,%5,%6,%7}, {%8,%9}, {%0,%1,%2,%3};\n"
        : "+f"(c[0]), "+f"(c[1]), "+f"(c[2]), "+f"(c[3])
        : "r"(a0), "r"(a1), "r"(a2), "r"(a3), "r"(b0), "r"(b1));
}
__device__ __forceinline__ uint32_t sw128(uint32_t off) { return off ^ ((off >> 3) & 0x70); }

// ---------- prologue ----------
// Packing: col n in [0,128) of CTA jt: unit u = n>>2, gate g = n&3.
// Original weight row = g*512 + jt*32 + u.
__global__ void pack_weights(
    const float* __restrict__ Wih0, const float* __restrict__ Whh0,
    const float* __restrict__ bih0, const float* __restrict__ bhh0,
    const float* __restrict__ Wih1, const float* __restrict__ Whh1,
    const float* __restrict__ bih1, const float* __restrict__ bhh1)
{
    int i0 = blockIdx.x * blockDim.x + threadIdx.x;
    int st = gridDim.x * blockDim.x;
    for (int i = i0; i < 16 * 128 * 512; i += st) {
        int jt = i >> 16, n = (i >> 9) & 127, k = i & 511;
        int row = (n & 3) * HH + jt * 32 + (n >> 2);
        g_Wp0[i] = __float2half_rn(Whh0[(size_t)row * HH + k]);
    }
    for (int i = i0; i < 16 * 128 * 1024; i += st) {
        int jt = i >> 17, n = (i >> 10) & 127, k = i & 1023;
        int row = (n & 3) * HH + jt * 32 + (n >> 2);
        float v = (k < HH) ? Wih1[(size_t)row * HH + k] : Whh1[(size_t)row * HH + k - HH];
        g_Wp1[i] = __float2half_rn(v);
    }
    for (int i = i0; i < 16 * 128 * 256; i += st) {
        int jt = i >> 15, n = (i >> 8) & 127, k = i & 255;
        int row = (n & 3) * HH + jt * 32 + (n >> 2);
        g_Wi0p[i] = (k < 254) ? __float2half_rn(Wih0[(size_t)row * 254 + k]) : __half(0);
    }
    for (int i = i0; i < 2048; i += st) {
        int jt = i >> 7, n = i & 127;
        int row = (n & 3) * HH + jt * 32 + (n >> 2);
        g_b0p[i] = bih0[row] + bhh0[row];
        g_b1p[i] = bih1[row] + bhh1[row];
    }
}

__global__ void build_x_init(
    const int* __restrict__ sl, const int* __restrict__ el,
    const float* __restrict__ sc, const float* __restrict__ ec,
    const float* __restrict__ emb)
{
    int i0 = blockIdx.x * blockDim.x + threadIdx.x;
    int st = gridDim.x * blockDim.x;
    for (int i = i0; i < NB * 256; i += st) {
        int b = i >> 8, k = i & 255;
        float v;
        if      (k < 64)  v = emb[sl[b] * 64 + k];
        else if (k < 128) v = emb[el[b] * 64 + (k - 64)];
        else if (k < 191) v = sc[b * 63 + (k - 128)];
        else if (k < 254) v = ec[b * 63 + (k - 191)];
        else              v = 0.f;
        g_xh[i] = __float2half_rn(v);
    }
    __half z = __half(0);
    for (int i = i0; i < NB * HH; i += st) {
        g_h0h[0][i] = z; g_h1a[i] = z; g_c0[i] = 0.f; g_c1[i] = 0.f;
    }
}

// ---------- fused GEMM + gates tile body ----------
// CTA: 128 rows x 128 cols. 8 warps as 4(row) x 2(col); warp tile 32x64.
// MODE 0: layer0 (K=512, add x0T rows)  MODE 1: layer1 (K=1024, add bias)
// MODE 2: x0 build (K=256, add bias, write x0T)
constexpr int STGB = 32768;
constexpr int SMEMSZ = 2 * STGB;

template<int MODE>
__device__ __forceinline__ void tile_body(
    const __half* __restrict__ A1, const __half* __restrict__ A2,
    const __half* __restrict__ Wp, const float* __restrict__ addv,
    float* __restrict__ cbuf, void* __restrict__ houtv, char* smem)
{
    const uint32_t sb = smem_u32(smem);
    const int tid = threadIdx.x, lane = tid & 31, wid = tid >> 5;
    const int wr = wid & 3, wc = wid >> 2;
    const int m0 = blockIdx.x * 128, jt = blockIdx.y;
    constexpr int KW  = (MODE == 0) ? 512 : (MODE == 1) ? 1024 : 256;
    constexpr int LDA = (MODE == 2) ? 256 : 512;
    constexpr int NT  = KW / 64;

    const __half* Bb = Wp + (size_t)jt * 128 * KW;

    auto copy_stage = [&](int s, int kt) {
        const uint32_t ab = sb + s * STGB, bbs = ab + 16384;
        const int k0 = kt * 64;
#pragma unroll
        for (int i = 0; i < 4; ++i) {
            int idx = tid + i * 256;
            int row = idx >> 3, ck = idx & 7;
            uint32_t sw = sw128(row * 128 + ck * 16);
            const __half* As = (MODE == 1 && k0 >= 512)
                ? A2 + (size_t)(m0 + row) * LDA + (k0 - 512) + ck * 8
                : A1 + (size_t)(m0 + row) * LDA + k0 + ck * 8;
            CP16(ab + sw, As);
            CP16(bbs + sw, Bb + (size_t)row * KW + k0 + ck * 8);
        }
    };

    float acc[2][8][4];
#pragma unroll
    for (int mt = 0; mt < 2; ++mt)
#pragma unroll
        for (int nt = 0; nt < 8; ++nt)
#pragma unroll
            for (int e = 0; e < 4; ++e) acc[mt][nt][e] = 0.f;

    copy_stage(0, 0);
    CP_COMMIT();

    const int q = lane >> 3, rr = lane & 7;
    for (int kt = 0; kt < NT; ++kt) {
        if (kt + 1 < NT) { copy_stage((kt + 1) & 1, kt + 1); CP_COMMIT(); CP_WAIT(1); }
        else CP_WAIT(0);
        __syncthreads();
        const uint32_t ab = sb + (kt & 1) * STGB, bbs = ab + 16384;
#pragma unroll
        for (int ks = 0; ks < 4; ++ks) {
            uint32_t a[2][4];
#pragma unroll
            for (int mt = 0; mt < 2; ++mt)
                LDSM_X4(a[mt][0], a[mt][1], a[mt][2], a[mt][3],
                    ab + sw128((wr * 32 + mt * 16 + (q & 1) * 8 + rr) * 128 + ks * 32 + (q >> 1) * 16));
#pragma unroll
            for (int nt2 = 0; nt2 < 4; ++nt2) {
                uint32_t b0, b1, b2, b3;
                LDSM_X4(b0, b1, b2, b3,
                    bbs + sw128((wc * 64 + nt2 * 16 + (q >> 1) * 8 + rr) * 128 + ks * 32 + (q & 1) * 16));
#pragma unroll
                for (int mt = 0; mt < 2; ++mt) {
                    hmma(acc[mt][nt2 * 2 + 0], a[mt][0], a[mt][1], a[mt][2], a[mt][3], b0, b1);
                    hmma(acc[mt][nt2 * 2 + 1], a[mt][0], a[mt][1], a[mt][2], a[mt][3], b2, b3);
                }
            }
        }
        __syncthreads();
    }

    // ---------- epilogue ----------
    const int q4 = lane & 3;
    const int rbase = m0 + wr * 32 + (lane >> 2);

#pragma unroll
    for (int mt = 0; mt < 2; ++mt)
#pragma unroll
        for (int nt = 0; nt < 8; ++nt) {
            float* a = acc[mt][nt];
            const int cc = wc * 64 + nt * 8 + q4 * 2;
            const int ng = jt * 128 + cc;
            const int r0 = rbase + mt * 16, r1 = r0 + 8;
            if (MODE == 0) {
                const float* xp  = addv + (size_t)ng * NB;
                const float* xp1 = xp + NB;
                a[0] += xp[r0]; a[1] += xp1[r0]; a[2] += xp[r1]; a[3] += xp1[r1];
            } else {
                float b0 = addv[ng], b1 = addv[ng + 1];
                a[0] += b0; a[1] += b1; a[2] += b0; a[3] += b1;
            }
            if (MODE == 2) {
                float* x0T = (float*)houtv;
                x0T[(size_t)ng * NB + r0]       = a[0];
                x0T[(size_t)(ng + 1) * NB + r0] = a[1];
                x0T[(size_t)ng * NB + r1]       = a[2];
                x0T[(size_t)(ng + 1) * NB + r1] = a[3];
            } else {
                // exchange gate pairs: q4 even holds (i,f); q4 odd holds (g,o)
                float t0 = __shfl_xor_sync(0xffffffffu, a[0], 1);
                float t1 = __shfl_xor_sync(0xffffffffu, a[1], 1);
                float t2 = __shfl_xor_sync(0xffffffffu, a[2], 1);
                float t3 = __shfl_xor_sync(0xffffffffu, a[3], 1);
                float pi, pf, pg, po;
                int row;
                if (q4 & 1) { pi = t2;   pf = t3;   pg = a[2]; po = a[3]; row = r1; }
                else        { pi = a[0]; pf = a[1]; pg = t0;   po = t1;   row = r0; }
                const int u = jt * 32 + (cc >> 2);
                float co = cbuf[(size_t)row * HH + u];
                float cv = sigm(pf) * co + sigm(pi) * tanhf(pg);
                cbuf[(size_t)row * HH + u] = cv;
                ((__half*)houtv)[(size_t)row * HH + u] = __float2half_rn(sigm(po) * tanhf(cv));
            }
        }
}

__global__ void __launch_bounds__(256, 2) x0_step()
{
    extern __shared__ char smem[];
    tile_body<2>(g_xh, nullptr, g_Wi0p, g_b0p, nullptr, g_x0T, smem);
}

// z (+ zoff) == 0 -> layer1(t); == 1 -> layer0(t+1)
__global__ void __launch_bounds__(256, 2) dual_step(
    const __half* __restrict__ h0_rd, __half* __restrict__ h0_wr,
    const __half* __restrict__ h1_rd, __half* __restrict__ h1_wr, int zoff)
{
    extern __shared__ char smem[];
    if ((int)blockIdx.z + zoff == 0)
        tile_body<1>(h0_rd, h1_rd, g_Wp1, g_b1p, g_c1, h1_wr, smem);
    else
        tile_body<0>(h0_rd, nullptr, g_Wp0, g_x0T, g_c0, h0_wr, smem);
}

// ---------- batched fc over all timesteps ----------
__global__ void fc_all(const __half* __restrict__ h1, const float* __restrict__ fcW,
                       const float* __restrict__ fcb, float* __restrict__ yout)
{
    __shared__ float sh[64 * 33];
    __shared__ float sw[64 * 33];
    const int tid = threadIdx.x;
    const size_t r0 = (size_t)blockIdx.x * 64;
    const int rs = tid & 15, cg = tid >> 4;
    float acc[4][4];
#pragma unroll
    for (int r = 0; r < 4; ++r)
#pragma unroll
        for (int c = 0; c < 4; ++c) acc[r][c] = 0.f;

    for (int k0 = 0; k0 < HH; k0 += 32) {
        {
            int rr = tid >> 2, seg = tid & 3;
            uint4 v = *reinterpret_cast<const uint4*>(&h1[(r0 + rr) * HH + k0 + seg * 8]);
            const __half2* hp = reinterpret_cast<const __half2*>(&v);
            float* d = &sh[rr * 33 + seg * 8];
#pragma unroll
            for (int m = 0; m < 4; ++m) {
                float2 f = __half22float2(hp[m]);
                d[2 * m] = f.x; d[2 * m + 1] = f.y;
            }
        }
        for (int q2 = tid; q2 < 64 * 32; q2 += 256) {
            int j = q2 >> 5, kk = q2 & 31;
            sw[j * 33 + kk] = (j < NJ) ? fcW[(size_t)j * HH + k0 + kk] : 0.f;
        }
        __syncthreads();
#pragma unroll
        for (int kk = 0; kk < 32; ++kk) {
            float hv[4], wv[4];
#pragma unroll
            for (int r = 0; r < 4; ++r) hv[r] = sh[(rs + r * 16) * 33 + kk];
#pragma unroll
            for (int c = 0; c < 4; ++c) wv[c] = sw[(cg * 4 + c) * 33 + kk];
#pragma unroll
            for (int r = 0; r < 4; ++r)
#pragma unroll
                for (int c = 0; c < 4; ++c) acc[r][c] += hv[r] * wv[c];
        }
        __syncthreads();
    }
#pragma unroll
    for (int r = 0; r < 4; ++r)
#pragma unroll
        for (int c = 0; c < 4; ++c) {
            int jj = cg * 4 + c;
            if (jj < NJ)
                yout[(r0 + rs + r * 16) * NJ + jj] = acc[r][c] + fcb[jj];
        }
}

// ---------- final transpose [t][b][j] -> [b][j][t] ----------
__global__ void transpose_y(const float* __restrict__ gy, float* __restrict__ out)
{
    __shared__ float sy[NSEQ * NJ];
    const int b = blockIdx.x;
    for (int q = threadIdx.x; q < NSEQ * NJ; q += blockDim.x)
        sy[q] = gy[(size_t)(q / NJ) * NB * NJ + (size_t)b * NJ + (q % NJ)];
    __syncthreads();
    for (int q = threadIdx.x; q < NSEQ * NJ; q += blockDim.x) {
        int j = q / NSEQ, t = q - j * NSEQ;
        out[(size_t)b * (NJ * NSEQ) + q] = sy[t * NJ + j];
    }
}

// ---------- host ----------
template <typename T>
static void* symaddr(T& sym) {
    void* p = nullptr;
    cudaGetSymbolAddress(&p, sym);
    return p;
}

extern "C" void kernel_launch(void* const* d_in, const int* in_sizes, int n_in,
                              void* d_out, int out_size)
{
    const int*   sl   = (const int*)  d_in[0];
    const int*   el   = (const int*)  d_in[1];
    const float* sc   = (const float*)d_in[2];
    const float* ec   = (const float*)d_in[3];
    const float* emb  = (const float*)d_in[4];
    const float* Wih0 = (const float*)d_in[5];
    const float* Whh0 = (const float*)d_in[6];
    const float* bih0 = (const float*)d_in[7];
    const float* bhh0 = (const float*)d_in[8];
    const float* Wih1 = (const float*)d_in[9];
    const float* Whh1 = (const float*)d_in[10];
    const float* bih1 = (const float*)d_in[11];
    const float* bhh1 = (const float*)d_in[12];
    const float* fcW  = (const float*)d_in[13];
    const float* fcb  = (const float*)d_in[14];
    float* out = (float*)d_out;

    __half* p_h0h = (__half*)symaddr(g_h0h);
    __half* p_h1a = (__half*)symaddr(g_h1a);
    float*  p_y   = (float*) symaddr(g_y);

    cudaFuncSetAttribute(x0_step,   cudaFuncAttributeMaxDynamicSharedMemorySize, SMEMSZ);
    cudaFuncSetAttribute(dual_step, cudaFuncAttributeMaxDynamicSharedMemorySize, SMEMSZ);

    pack_weights<<<256, 256>>>(Wih0, Whh0, bih0, bhh0, Wih1, Whh1, bih1, bhh1);
    build_x_init<<<256, 256>>>(sl, el, sc, ec, emb);

    const size_t NH = (size_t)NB * HH;
    x0_step<<<dim3(32, 16, 1), 256, SMEMSZ>>>();

    // L0(0): reads h0h[0] (zeros), writes h0h[1]
    dual_step<<<dim3(32, 16, 1), 256, SMEMSZ>>>(p_h0h, p_h0h + NH, nullptr, nullptr, 1);

    for (int t = 0; t < NSEQ - 1; ++t) {
        const int src = (t & 1) ^ 1;     // h0 produced by L0(t)
        dual_step<<<dim3(32, 16, 2), 256, SMEMSZ>>>(
            p_h0h + (size_t)src * NH,          // A1 for both parts
            p_h0h + (size_t)(t & 1) * NH,      // L0(t+1) output
            p_h1a + (size_t)t * NH,            // h1(t-1 history slot t)
            p_h1a + (size_t)(t + 1) * NH, 0);  // h1(t) -> slot t+1
    }
    // L1(99): h0 from L0(99) is in h0h[(99&1)^1] = h0h[0]
    dual_step<<<dim3(32, 16, 1), 256, SMEMSZ>>>(
        p_h0h, nullptr, p_h1a + (size_t)(NSEQ - 1) * NH, p_h1a + (size_t)NSEQ * NH, 0);

    fc_all<<<NSEQ * 64, 256>>>(p_h1a + NH, fcW, fcb, p_y);
    transpose_y<<<NB, 256>>>(p_y, out);
}